// round 13
// baseline (speedup 1.0000x reference)
#include <cuda_runtime.h>
#include <cuda_bf16.h>

// Problem constants
#define BB   64      // batch (inputs)
#define MM   256     // modes
#define KK   4096    // spatial (64*64)

#define KC      128  // K per CTA tile
#define KSPLIT  32   // KK / KC (norm + dot granularity)
#define MT      64   // modes per CTA
#define MTILES  4    // MM / MT
#define NTHR    256  // 8 warps = 2(m) x 2(n) x 2(k-half)
#define NCTA    (MTILES * KSPLIT)   // 128 CTAs, single co-resident wave
#define ROWF    132  // padded floats per smem row (conflict-free fragments)
#define ROW4    33   // float4 units per row
// A tile + B tile + k-half reduction area (4 pairs x 32 lanes x 32 floats)
#define REDOFF  (2 * BB * ROWF)
#define SMEMB   ((2 * BB * ROWF + 4096) * 4)   // 83968 bytes
#define EPS_C   0.0009f

// Deterministic partial buffers (no cudaMalloc allowed)
__device__ __align__(16) float g_dot[KSPLIT * BB * MM];   // [s][b][m]  2 MB
__device__ __align__(16) float g_fss[KSPLIT * BB];        // [s][b]
__device__ __align__(16) float g_mss[KSPLIT * MM];        // [s][m]
__device__ unsigned int g_cnt;    // arrival counter (reset by last CTA)
__device__ unsigned int g_go;     // release flag     (reset after tail)
__device__ unsigned int g_done;   // tail-done counter

__device__ __forceinline__ void cp_async16(void* smem, const void* gmem) {
    unsigned int s = (unsigned int)__cvta_generic_to_shared(smem);
    asm volatile("cp.async.cg.shared.global [%0], [%1], 16;"
                 :: "r"(s), "l"(gmem));
}

// mma.tf32 fed with RAW f32 bits (HW reads sign/exp/top-10-mantissa =
// round-toward-zero tf32; CUTLASS-sanctioned mode).
__device__ __forceinline__ void mma_tf32(float& d0, float& d1, float& d2, float& d3,
                                         unsigned int a0, unsigned int a1,
                                         unsigned int a2, unsigned int a3,
                                         unsigned int b0, unsigned int b1) {
    asm volatile(
        "mma.sync.aligned.m16n8k8.row.col.f32.tf32.tf32.f32 "
        "{%0,%1,%2,%3}, {%4,%5,%6,%7}, {%8,%9}, {%0,%1,%2,%3};"
        : "+f"(d0), "+f"(d1), "+f"(d2), "+f"(d3)
        : "r"(a0), "r"(a1), "r"(a2), "r"(a3), "r"(b0), "r"(b1));
}

// Fused: tf32 tensor-core GEMM partials + last-64-to-arrive finalize.
__global__ __launch_bounds__(NTHR)
void fused_kernel(const float* __restrict__ inp,
                  const float* __restrict__ mds,
                  float* __restrict__ out) {
    extern __shared__ unsigned int su[];
    unsigned int* Au = su;                 // A tile: 64 x 132 raw f32 bits
    unsigned int* Bu = su + BB * ROWF;     // B tile: 64 x 132
    float4* racc = reinterpret_cast<float4*>(su + REDOFF);  // k-half reduction
    __shared__ float4 sd4[4][MM / 4];      // finalize: dot combine
    __shared__ float4 sm4[4][MM / 4];      // finalize: mss combine
    __shared__ float  sf[4];
    __shared__ float  red[2];
    __shared__ unsigned int s_rank;

    const int mt = blockIdx.x;
    const int ks = blockIdx.y;
    const int kbase = ks * KC;
    const int mbase = mt * MT;
    const int tid  = threadIdx.x;
    const int lane = tid & 31;
    const int w    = tid >> 5;             // 0..7
    const int g    = lane >> 2;            // groupID 0..7
    const int tig  = lane & 3;             // thread-in-group 0..3

    uint4* Au4 = reinterpret_cast<uint4*>(Au);
    uint4* Bu4 = reinterpret_cast<uint4*>(Bu);

    // ---- stage A+B via cp.async (no LDG-wait, no CVT, no STS chain) ----
#pragma unroll
    for (int i = 0; i < 8; ++i) {
        int j  = i * NTHR + tid;
        int b  = j >> 5;
        int kq = j & 31;
        cp_async16(&Au4[b * ROW4 + kq],
                   reinterpret_cast<const float4*>(inp + (size_t)b * KK + kbase) + kq);
    }
#pragma unroll
    for (int i = 0; i < 8; ++i) {
        int j  = i * NTHR + tid;
        int m  = j >> 5;
        int kq = j & 31;
        cp_async16(&Bu4[m * ROW4 + kq],
                   reinterpret_cast<const float4*>(mds + (size_t)(mbase + m) * KK + kbase) + kq);
    }
    asm volatile("cp.async.commit_group;");
    asm volatile("cp.async.wait_group 0;");
    __syncthreads();

    // ---- tensor-core main loop: m32 x n32 x k64 warp tiles ----
    const int kh = w >> 2;                 // k-half 0/1
    const int wm = w & 1;                  // m-half
    const int wn = (w >> 1) & 1;           // n-half
    const int wp = w & 3;                  // warp-pair id (same for kh 0/1)
    const int r0 = wm * 32;                // A row base
    const int n0 = wn * 32;                // B col base (within 64-mode slice)
    const int kb = kh * 64;                // k base (floats)

    float acc[2][4][4];                    // [mi][t][frag]
#pragma unroll
    for (int mi = 0; mi < 2; ++mi)
#pragma unroll
        for (int t = 0; t < 4; ++t)
#pragma unroll
            for (int i = 0; i < 4; ++i) acc[mi][t][i] = 0.f;

#pragma unroll 4
    for (int kk = 0; kk < 8; ++kk) {
        const int acol = kb + kk * 8 + tig;
        unsigned int a[2][4];
#pragma unroll
        for (int mi = 0; mi < 2; ++mi) {
            int row = r0 + 16 * mi + g;
            a[mi][0] = Au[row       * ROWF + acol];
            a[mi][1] = Au[(row + 8) * ROWF + acol];
            a[mi][2] = Au[row       * ROWF + acol + 4];
            a[mi][3] = Au[(row + 8) * ROWF + acol + 4];
        }
#pragma unroll
        for (int t = 0; t < 4; ++t) {
            int n = n0 + t * 8 + g;
            unsigned int b0 = Bu[n * ROWF + kb + kk * 8 + tig];
            unsigned int b1 = Bu[n * ROWF + kb + kk * 8 + tig + 4];
#pragma unroll
            for (int mi = 0; mi < 2; ++mi)
                mma_tf32(acc[mi][t][0], acc[mi][t][1], acc[mi][t][2], acc[mi][t][3],
                         a[mi][0], a[mi][1], a[mi][2], a[mi][3], b0, b1);
        }
    }

    // ---- k-half reduction in smem: kh=1 stores, kh=0 adds ----
    // racc layout: [pair][i4 0..7][lane] float4 -> conflict-free 128-bit ops
    if (kh == 1) {
#pragma unroll
        for (int mi = 0; mi < 2; ++mi)
#pragma unroll
            for (int t = 0; t < 4; ++t)
                racc[(wp * 8 + mi * 4 + t) * 32 + lane] =
                    make_float4(acc[mi][t][0], acc[mi][t][1],
                                acc[mi][t][2], acc[mi][t][3]);
    }
    __syncthreads();

    if (kh == 0) {
        // ---- epilogue: full-tile dot, split slot = ks ----
#pragma unroll
        for (int mi = 0; mi < 2; ++mi)
#pragma unroll
            for (int t = 0; t < 4; ++t) {
                float4 o = racc[(wp * 8 + mi * 4 + t) * 32 + lane];
                float d0 = acc[mi][t][0] + o.x;
                float d1 = acc[mi][t][1] + o.y;
                float d2 = acc[mi][t][2] + o.z;
                float d3 = acc[mi][t][3] + o.w;
                int row = r0 + 16 * mi + g;
                int m = mbase + n0 + t * 8 + 2 * tig;
                *reinterpret_cast<float2*>(&g_dot[((size_t)ks * BB + row)     * MM + m]) =
                    make_float2(d0, d1);
                *reinterpret_cast<float2*>(&g_dot[((size_t)ks * BB + row + 8) * MM + m]) =
                    make_float2(d2, d3);
            }
    }

    // ---- partial squared norms from RAW f32 tiles (warp per row) ----
    const float4* Af4 = reinterpret_cast<const float4*>(Au);
    const float4* Bf4 = reinterpret_cast<const float4*>(Bu);
#pragma unroll
    for (int r = 0; r < 8; ++r) {
        int m = 8 * w + r;
        float4 v = Bf4[m * ROW4 + lane];
        float s = v.x * v.x + v.y * v.y + v.z * v.z + v.w * v.w;
#pragma unroll
        for (int o = 16; o > 0; o >>= 1) s += __shfl_xor_sync(0xffffffffu, s, o);
        if (lane == 0) g_mss[ks * MM + mbase + m] = s;
    }
    if (mt == 0) {
#pragma unroll
        for (int r = 0; r < 8; ++r) {
            int b = 8 * w + r;
            float4 v = Af4[b * ROW4 + lane];
            float s = v.x * v.x + v.y * v.y + v.z * v.z + v.w * v.w;
#pragma unroll
            for (int o = 16; o > 0; o >>= 1) s += __shfl_xor_sync(0xffffffffu, s, o);
            if (lane == 0) g_fss[ks * BB + b] = s;
        }
    }

    // ---- arrival: last 64 CTAs become finalizers (one b each) ----
    __syncthreads();
    if (tid == 0) {
        __threadfence();                                   // publish partials
        s_rank = atomicAdd(&g_cnt, 1u);
    }
    __syncthreads();
    const unsigned int rank = s_rank;

    if (rank < NCTA - BB) return;

    if (tid == 0) {
        if (rank == NCTA - 1) {                            // true last arriver
            g_cnt = 0;                                     // reset for next replay
            __threadfence();
            atomicExch(&g_go, 1u);                         // release
        } else {
            unsigned int v;
            do {
                asm volatile("ld.acquire.gpu.u32 %0, [%1];"
                             : "=r"(v) : "l"(&g_go));
            } while (v == 0u);
        }
    }
    __syncthreads();

    // ---- finalize b: thread = (m-quad q, split-group sg) ----
    const int b  = (int)rank - (NCTA - BB);
    const int q  = tid & 63;                               // m-quad 0..63
    const int sg = tid >> 6;                               // group 0..3

    const float4* dot4 = reinterpret_cast<const float4*>(g_dot);
    const float4* mss4 = reinterpret_cast<const float4*>(g_mss);

    float4 d = make_float4(0.f, 0.f, 0.f, 0.f);
    float4 ms = make_float4(0.f, 0.f, 0.f, 0.f);
    float fs = 0.f;
#pragma unroll
    for (int i = 0; i < 8; ++i) {                          // 8 of 32 splits
        int s = sg * 8 + i;
        float4 v = dot4[((size_t)s * BB + b) * (MM / 4) + q];
        d.x += v.x; d.y += v.y; d.z += v.z; d.w += v.w;
        float4 u = mss4[s * (MM / 4) + q];
        ms.x += u.x; ms.y += u.y; ms.z += u.z; ms.w += u.w;
        fs += g_fss[s * BB + b];                           // uniform -> broadcast
    }
    sd4[sg][q] = d;
    sm4[sg][q] = ms;
    if (q == 0) sf[sg] = fs;
    __syncthreads();

    if (sg == 0) {
        float4 d0 = sd4[0][q], d1 = sd4[1][q], d2 = sd4[2][q], d3 = sd4[3][q];
        float4 m0 = sm4[0][q], m1 = sm4[1][q], m2 = sm4[2][q], m3 = sm4[3][q];
        float dot[4] = { d0.x + d1.x + d2.x + d3.x, d0.y + d1.y + d2.y + d3.y,
                         d0.z + d1.z + d2.z + d3.z, d0.w + d1.w + d2.w + d3.w };
        float mss[4] = { m0.x + m1.x + m2.x + m3.x, m0.y + m1.y + m2.y + m3.y,
                         m0.z + m1.z + m2.z + m3.z, m0.w + m1.w + m2.w + m3.w };
        float fss = sf[0] + sf[1] + sf[2] + sf[3];
        float fn = sqrtf(fss);

        float best = 3.4e38f;
#pragma unroll
        for (int i = 0; i < 4; ++i) {
            float mn = sqrtf(mss[i]);
            float cc = dot[i] / (fn * mn);
            float dn = sqrtf(fmaxf(2.f - 2.f * cc, 0.f));
            float lum = (2.f * fn * mn + EPS_C) / (fss + mss[i] + EPS_C);
            float metric = (1.f - (2.f - dn) * 0.5f * sqrtf(lum)) * 2.f;
            best = fminf(best, metric);
        }
#pragma unroll
        for (int o = 16; o > 0; o >>= 1)
            best = fminf(best, __shfl_xor_sync(0xffffffffu, best, o));
        if ((tid & 31) == 0) red[tid >> 5] = best;
    }
    __syncthreads();
    if (tid == 0) {
        out[b] = fminf(red[0], red[1]);

        unsigned int dn = atomicAdd(&g_done, 1u);          // last finalizer resets
        if (dn == BB - 1) {
            g_done = 0u;
            atomicExch(&g_go, 0u);
        }
    }
}

extern "C" void kernel_launch(void* const* d_in, const int* in_sizes, int n_in,
                              void* d_out, int out_size) {
    const float* inp = (const float*)d_in[0];
    const float* mds = (const float*)d_in[1];
    if (in_sizes[0] > in_sizes[1]) {   // identify by element count
        const float* t = inp; inp = mds; mds = t;
    }

    cudaFuncSetAttribute(fused_kernel,
                         cudaFuncAttributeMaxDynamicSharedMemorySize, SMEMB);

    dim3 grid(MTILES, KSPLIT);         // 4 x 32 = 128 CTAs, single wave
    fused_kernel<<<grid, NTHR, SMEMB>>>(inp, mds, (float*)d_out);
}

// round 14
// speedup vs baseline: 1.1905x; 1.1905x over previous
#include <cuda_runtime.h>
#include <cuda_bf16.h>

// Problem constants
#define BB   64      // batch (inputs)
#define MM   256     // modes
#define KK   4096    // spatial (64*64)

#define KC      128  // K per CTA tile
#define KSPLIT  32   // KK / KC (norm + dot granularity)
#define MT      64   // modes per CTA
#define MTILES  4    // MM / MT
#define NTHR    256  // 8 warps = 2(m) x 2(n) x 2(k-half)
#define NCTA    (MTILES * KSPLIT)   // 128 CTAs, single co-resident wave
#define ROWF    132  // padded floats per smem row (conflict-free fragments)
#define ROW4    33   // float4 units per row
#define REDOFF  (2 * BB * ROWF)
#define SMEMB   ((2 * BB * ROWF + 4096) * 4)   // 83968 bytes
#define EPS_C   0.0009f

// Deterministic partial buffers (no cudaMalloc allowed)
__device__ __align__(16) float g_dot[KSPLIT * BB * MM];   // [s][b][m]  2 MB
__device__ __align__(16) float g_fss[KSPLIT * BB];        // [s][b]
__device__ __align__(16) float g_mss[KSPLIT * MM];        // [s][m]
__device__ unsigned int g_cnt;    // arrival counter (reset by last finalizer)
__device__ unsigned int g_done;   // tail-done counter

__device__ __forceinline__ void cp_async16(void* smem, const void* gmem) {
    unsigned int s = (unsigned int)__cvta_generic_to_shared(smem);
    asm volatile("cp.async.cg.shared.global [%0], [%1], 16;"
                 :: "r"(s), "l"(gmem));
}

// mma.tf32 fed with RAW f32 bits (HW reads sign/exp/top-10-mantissa =
// round-toward-zero tf32; CUTLASS-sanctioned mode).
__device__ __forceinline__ void mma_tf32(float& d0, float& d1, float& d2, float& d3,
                                         unsigned int a0, unsigned int a1,
                                         unsigned int a2, unsigned int a3,
                                         unsigned int b0, unsigned int b1) {
    asm volatile(
        "mma.sync.aligned.m16n8k8.row.col.f32.tf32.tf32.f32 "
        "{%0,%1,%2,%3}, {%4,%5,%6,%7}, {%8,%9}, {%0,%1,%2,%3};"
        : "+f"(d0), "+f"(d1), "+f"(d2), "+f"(d3)
        : "r"(a0), "r"(a1), "r"(a2), "r"(a3), "r"(b0), "r"(b1));
}

// Fused: tf32 tensor-core GEMM partials + all-128-CTA finalize
// (each CTA: one b, one 128-mode half; atomicMin into out).
__global__ __launch_bounds__(NTHR)
void fused_kernel(const float* __restrict__ inp,
                  const float* __restrict__ mds,
                  unsigned int* __restrict__ outu) {
    extern __shared__ unsigned int su[];
    unsigned int* Au = su;                 // A tile: 64 x 132 raw f32 bits
    unsigned int* Bu = su + BB * ROWF;     // B tile: 64 x 132
    float4* racc = reinterpret_cast<float4*>(su + REDOFF);  // k-half reduction
    __shared__ float4 sd4[8][32];          // finalize: dot combine
    __shared__ float4 sm4[8][32];          // finalize: mss combine
    __shared__ float  sf[8];
    __shared__ unsigned int s_rank;

    const int mt = blockIdx.x;
    const int ks = blockIdx.y;
    const int kbase = ks * KC;
    const int mbase = mt * MT;
    const int tid  = threadIdx.x;
    const int lane = tid & 31;
    const int w    = tid >> 5;             // 0..7
    const int g    = lane >> 2;            // groupID 0..7
    const int tig  = lane & 3;             // thread-in-group 0..3

    // per-replay out init (visible to finalizers via the arrival fence below)
    if (mt == 0 && ks == 0 && tid < BB) outu[tid] = 0x7f7f7f7fu;

    uint4* Au4 = reinterpret_cast<uint4*>(Au);
    uint4* Bu4 = reinterpret_cast<uint4*>(Bu);

    // ---- stage A+B via cp.async ----
#pragma unroll
    for (int i = 0; i < 8; ++i) {
        int j  = i * NTHR + tid;
        int b  = j >> 5;
        int kq = j & 31;
        cp_async16(&Au4[b * ROW4 + kq],
                   reinterpret_cast<const float4*>(inp + (size_t)b * KK + kbase) + kq);
    }
#pragma unroll
    for (int i = 0; i < 8; ++i) {
        int j  = i * NTHR + tid;
        int m  = j >> 5;
        int kq = j & 31;
        cp_async16(&Bu4[m * ROW4 + kq],
                   reinterpret_cast<const float4*>(mds + (size_t)(mbase + m) * KK + kbase) + kq);
    }
    asm volatile("cp.async.commit_group;");
    asm volatile("cp.async.wait_group 0;");
    __syncthreads();

    // ---- tensor-core main loop: m32 x n32 x k64 warp tiles ----
    const int kh = w >> 2;                 // k-half 0/1
    const int wm = w & 1;                  // m-half
    const int wn = (w >> 1) & 1;           // n-half
    const int wp = w & 3;                  // warp-pair id (same for kh 0/1)
    const int r0 = wm * 32;                // A row base
    const int n0 = wn * 32;                // B col base (within 64-mode slice)
    const int kb = kh * 64;                // k base (floats)

    float acc[2][4][4];                    // [mi][t][frag]
#pragma unroll
    for (int mi = 0; mi < 2; ++mi)
#pragma unroll
        for (int t = 0; t < 4; ++t)
#pragma unroll
            for (int i = 0; i < 4; ++i) acc[mi][t][i] = 0.f;

#pragma unroll 4
    for (int kk = 0; kk < 8; ++kk) {
        const int acol = kb + kk * 8 + tig;
        unsigned int a[2][4];
#pragma unroll
        for (int mi = 0; mi < 2; ++mi) {
            int row = r0 + 16 * mi + g;
            a[mi][0] = Au[row       * ROWF + acol];
            a[mi][1] = Au[(row + 8) * ROWF + acol];
            a[mi][2] = Au[row       * ROWF + acol + 4];
            a[mi][3] = Au[(row + 8) * ROWF + acol + 4];
        }
#pragma unroll
        for (int t = 0; t < 4; ++t) {
            int n = n0 + t * 8 + g;
            unsigned int b0 = Bu[n * ROWF + kb + kk * 8 + tig];
            unsigned int b1 = Bu[n * ROWF + kb + kk * 8 + tig + 4];
#pragma unroll
            for (int mi = 0; mi < 2; ++mi)
                mma_tf32(acc[mi][t][0], acc[mi][t][1], acc[mi][t][2], acc[mi][t][3],
                         a[mi][0], a[mi][1], a[mi][2], a[mi][3], b0, b1);
        }
    }

    // ---- k-half reduction in smem: kh=1 stores, kh=0 adds ----
    if (kh == 1) {
#pragma unroll
        for (int mi = 0; mi < 2; ++mi)
#pragma unroll
            for (int t = 0; t < 4; ++t)
                racc[(wp * 8 + mi * 4 + t) * 32 + lane] =
                    make_float4(acc[mi][t][0], acc[mi][t][1],
                                acc[mi][t][2], acc[mi][t][3]);
    }
    __syncthreads();

    if (kh == 0) {
        // ---- epilogue: full-tile dot, split slot = ks ----
#pragma unroll
        for (int mi = 0; mi < 2; ++mi)
#pragma unroll
            for (int t = 0; t < 4; ++t) {
                float4 o = racc[(wp * 8 + mi * 4 + t) * 32 + lane];
                float d0 = acc[mi][t][0] + o.x;
                float d1 = acc[mi][t][1] + o.y;
                float d2 = acc[mi][t][2] + o.z;
                float d3 = acc[mi][t][3] + o.w;
                int row = r0 + 16 * mi + g;
                int m = mbase + n0 + t * 8 + 2 * tig;
                *reinterpret_cast<float2*>(&g_dot[((size_t)ks * BB + row)     * MM + m]) =
                    make_float2(d0, d1);
                *reinterpret_cast<float2*>(&g_dot[((size_t)ks * BB + row + 8) * MM + m]) =
                    make_float2(d2, d3);
            }
    }

    // ---- partial squared norms from RAW f32 tiles (warp per row) ----
    const float4* Af4 = reinterpret_cast<const float4*>(Au);
    const float4* Bf4 = reinterpret_cast<const float4*>(Bu);
#pragma unroll
    for (int r = 0; r < 8; ++r) {
        int m = 8 * w + r;
        float4 v = Bf4[m * ROW4 + lane];
        float s = v.x * v.x + v.y * v.y + v.z * v.z + v.w * v.w;
#pragma unroll
        for (int o = 16; o > 0; o >>= 1) s += __shfl_xor_sync(0xffffffffu, s, o);
        if (lane == 0) g_mss[ks * MM + mbase + m] = s;
    }
    if (mt == 0) {
#pragma unroll
        for (int r = 0; r < 8; ++r) {
            int b = 8 * w + r;
            float4 v = Af4[b * ROW4 + lane];
            float s = v.x * v.x + v.y * v.y + v.z * v.z + v.w * v.w;
#pragma unroll
            for (int o = 16; o > 0; o >>= 1) s += __shfl_xor_sync(0xffffffffu, s, o);
            if (lane == 0) g_fss[ks * BB + b] = s;
        }
    }

    // ---- arrival + direct-poll release (no separate flag hop) ----
    __syncthreads();
    if (tid == 0) {
        __threadfence();                                   // publish partials
        s_rank = atomicAdd(&g_cnt, 1u);                    // arrival rank
        unsigned int v;
        do {                                               // wait for all arrivals
            asm volatile("ld.acquire.gpu.u32 %0, [%1];" : "=r"(v) : "l"(&g_cnt));
        } while (v < NCTA);
    }
    __syncthreads();
    const unsigned int rank = s_rank;

    // ---- finalize: CTA handles b = rank&63, mode-half mh = rank>>6 ----
    const int b  = rank & 63;
    const int mh = rank >> 6;                              // 0/1
    const int q  = mh * 32 + lane;                         // m-quad in [0,64)
    const int sg = w;                                      // split-group 0..7

    const float4* dot4 = reinterpret_cast<const float4*>(g_dot);
    const float4* mss4 = reinterpret_cast<const float4*>(g_mss);

    float4 d  = make_float4(0.f, 0.f, 0.f, 0.f);
    float4 ms = make_float4(0.f, 0.f, 0.f, 0.f);
    float  fs = 0.f;
#pragma unroll
    for (int i = 0; i < 4; ++i) {                          // 4 of 32 splits
        int s = sg * 4 + i;
        float4 v = dot4[((size_t)s * BB + b) * (MM / 4) + q];
        d.x += v.x; d.y += v.y; d.z += v.z; d.w += v.w;
        float4 u = mss4[s * (MM / 4) + q];
        ms.x += u.x; ms.y += u.y; ms.z += u.z; ms.w += u.w;
        fs += g_fss[s * BB + b];                           // uniform -> broadcast
    }
    sd4[sg][lane] = d;
    sm4[sg][lane] = ms;
    if (lane == 0) sf[sg] = fs;
    __syncthreads();

    if (w == 0) {                                          // one warp combines
        float dot[4] = {0.f, 0.f, 0.f, 0.f};
        float mss[4] = {0.f, 0.f, 0.f, 0.f};
        float fss = 0.f;
#pragma unroll
        for (int i = 0; i < 8; ++i) {
            float4 dv = sd4[i][lane];
            float4 mv = sm4[i][lane];
            dot[0] += dv.x; dot[1] += dv.y; dot[2] += dv.z; dot[3] += dv.w;
            mss[0] += mv.x; mss[1] += mv.y; mss[2] += mv.z; mss[3] += mv.w;
            fss += sf[i];
        }
        float fn = sqrtf(fss);

        float best = 3.4e38f;
#pragma unroll
        for (int i = 0; i < 4; ++i) {
            float mn = sqrtf(mss[i]);
            float cc = dot[i] / (fn * mn);
            float dn = sqrtf(fmaxf(2.f - 2.f * cc, 0.f));
            float lum = (2.f * fn * mn + EPS_C) / (fss + mss[i] + EPS_C);
            float metric = (1.f - (2.f - dn) * 0.5f * sqrtf(lum)) * 2.f;
            best = fminf(best, metric);
        }
#pragma unroll
        for (int o = 16; o > 0; o >>= 1)
            best = fminf(best, __shfl_xor_sync(0xffffffffu, best, o));
        if (lane == 0) {
            atomicMin(&outu[b], __float_as_uint(best));    // nonneg: uint==float order

            unsigned int dn = atomicAdd(&g_done, 1u);      // last finalizer resets
            if (dn == NCTA - 1) {
                g_done = 0u;
                atomicExch(&g_cnt, 0u);
            }
        }
    }
}

extern "C" void kernel_launch(void* const* d_in, const int* in_sizes, int n_in,
                              void* d_out, int out_size) {
    const float* inp = (const float*)d_in[0];
    const float* mds = (const float*)d_in[1];
    if (in_sizes[0] > in_sizes[1]) {   // identify by element count
        const float* t = inp; inp = mds; mds = t;
    }

    cudaFuncSetAttribute(fused_kernel,
                         cudaFuncAttributeMaxDynamicSharedMemorySize, SMEMB);

    dim3 grid(MTILES, KSPLIT);         // 4 x 32 = 128 CTAs, single wave
    fused_kernel<<<grid, NTHR, SMEMB>>>(inp, mds, (unsigned int*)d_out);
}